// round 6
// baseline (speedup 1.0000x reference)
#include <cuda_runtime.h>
#include <cuda_bf16.h>
#include <mma.h>
#include <cstdint>

using namespace nvcuda;

#define BATCH 2
#define SEQ   2048
#define HID   768
#define NHEAD 12
#define HDIM  64
#define MTOK  (BATCH*SEQ)
#define GAMMA 0.05f
#define LNEPS 1e-12f

typedef unsigned long long u64;

// ---------- packed f32x2 helpers ----------
__device__ __forceinline__ void fma2(u64& d, u64 a, u64 b) {
    asm("fma.rn.f32x2 %0, %1, %2, %0;" : "+l"(d) : "l"(a), "l"(b));
}
__device__ __forceinline__ u64 dup2(float x) {
    u64 r; asm("mov.b64 %0, {%1, %1};" : "=l"(r) : "f"(x)); return r;
}
__device__ __forceinline__ float2 unpk2(u64 v) {
    float2 r; asm("mov.b64 {%0, %1}, %2;" : "=f"(r.x), "=f"(r.y) : "l"(v)); return r;
}

// ---------------- scratch ----------------
__device__ __nv_bfloat16 g_qhi[MTOK*HID];
__device__ __nv_bfloat16 g_qlo[MTOK*HID];
__device__ __nv_bfloat16 g_khi[MTOK*HID];
__device__ __nv_bfloat16 g_klo[MTOK*HID];
__device__ __nv_bfloat16 g_vb [MTOK*HID];
__device__ float g_ctx[MTOK*HID];
__device__ float g_y[MTOK*HID];

// ============ projection GEMM: C = A @ W^T + bias (+res) ============
__global__ __launch_bounds__(256, 2)
void proj_gemm(const float* __restrict__ A, const float* __restrict__ W,
               const float* __restrict__ bias, const float* __restrict__ res,
               float* __restrict__ C,
               __nv_bfloat16* __restrict__ hi, __nv_bfloat16* __restrict__ lo,
               __nv_bfloat16* __restrict__ bs,
               int gamma_mode)
{
    __shared__ float As[32][132];
    __shared__ float Ws[32][68];
    const int tid = threadIdx.x;
    const int tx = tid & 15, ty = tid >> 4;
    const int bm = blockIdx.x * 128;
    const int bn = blockIdx.y * 64;
    u64 acc2[8][2] = {};

    const float* Abase = A + (size_t)bm * HID;
    const float* Wbase = W + (size_t)bn * HID;

    for (int k0 = 0; k0 < HID; k0 += 32) {
        #pragma unroll
        for (int i = 0; i < 4; i++) {
            int f4 = tid + i * 256;
            int m = f4 >> 3, kk = (f4 & 7) * 4;
            float4 v = *(const float4*)(Abase + (size_t)m * HID + k0 + kk);
            As[kk + 0][m] = v.x; As[kk + 1][m] = v.y;
            As[kk + 2][m] = v.z; As[kk + 3][m] = v.w;
        }
        #pragma unroll
        for (int i = 0; i < 2; i++) {
            int f4 = tid + i * 256;
            int n = f4 >> 3, kk = (f4 & 7) * 4;
            float4 v = *(const float4*)(Wbase + (size_t)n * HID + k0 + kk);
            if (gamma_mode) {
                v.x += GAMMA * fmaxf(v.x, 0.f); v.y += GAMMA * fmaxf(v.y, 0.f);
                v.z += GAMMA * fmaxf(v.z, 0.f); v.w += GAMMA * fmaxf(v.w, 0.f);
            }
            Ws[kk + 0][n] = v.x; Ws[kk + 1][n] = v.y;
            Ws[kk + 2][n] = v.z; Ws[kk + 3][n] = v.w;
        }
        __syncthreads();
        #pragma unroll
        for (int k = 0; k < 32; k++) {
            float4 a0 = *(const float4*)&As[k][ty * 8];
            float4 a1 = *(const float4*)&As[k][ty * 8 + 4];
            ulonglong2 wp = *(const ulonglong2*)&Ws[k][tx * 4];
            float a[8] = {a0.x, a0.y, a0.z, a0.w, a1.x, a1.y, a1.z, a1.w};
            #pragma unroll
            for (int i = 0; i < 8; i++) {
                u64 ad = dup2(a[i]);
                fma2(acc2[i][0], ad, wp.x);
                fma2(acc2[i][1], ad, wp.y);
            }
        }
        __syncthreads();
    }

    float4 b = *(const float4*)(bias + bn + tx * 4);
    if (gamma_mode) {
        b.x += GAMMA * fmaxf(b.x, 0.f); b.y += GAMMA * fmaxf(b.y, 0.f);
        b.z += GAMMA * fmaxf(b.z, 0.f); b.w += GAMMA * fmaxf(b.w, 0.f);
    }
    #pragma unroll
    for (int i = 0; i < 8; i++) {
        int m = bm + ty * 8 + i;
        size_t base = (size_t)m * HID + bn + tx * 4;
        float2 c0 = unpk2(acc2[i][0]), c1 = unpk2(acc2[i][1]);
        float4 o;
        o.x = c0.x + b.x; o.y = c0.y + b.y;
        o.z = c1.x + b.z; o.w = c1.y + b.w;
        if (res) {
            float4 r = *(const float4*)(res + base);
            o.x += r.x; o.y += r.y; o.z += r.z; o.w += r.w;
        }
        if (C) *(float4*)(C + base) = o;
        if (hi) {
            __nv_bfloat16 h0 = __float2bfloat16(o.x), h1 = __float2bfloat16(o.y);
            __nv_bfloat16 h2 = __float2bfloat16(o.z), h3 = __float2bfloat16(o.w);
            __nv_bfloat16 l0 = __float2bfloat16(o.x - __bfloat162float(h0));
            __nv_bfloat16 l1 = __float2bfloat16(o.y - __bfloat162float(h1));
            __nv_bfloat16 l2 = __float2bfloat16(o.z - __bfloat162float(h2));
            __nv_bfloat16 l3 = __float2bfloat16(o.w - __bfloat162float(h3));
            __nv_bfloat162 hp0 = __halves2bfloat162(h0, h1), hp1 = __halves2bfloat162(h2, h3);
            __nv_bfloat162 lp0 = __halves2bfloat162(l0, l1), lp1 = __halves2bfloat162(l2, l3);
            uint2 hu, lu;
            hu.x = *(uint32_t*)&hp0; hu.y = *(uint32_t*)&hp1;
            lu.x = *(uint32_t*)&lp0; lu.y = *(uint32_t*)&lp1;
            *(uint2*)(hi + base) = hu;
            *(uint2*)(lo + base) = lu;
        }
        if (bs) {
            __nv_bfloat162 p0 = __floats2bfloat162_rn(o.x, o.y);
            __nv_bfloat162 p1 = __floats2bfloat162_rn(o.z, o.w);
            uint2 u;
            u.x = *(uint32_t*)&p0; u.y = *(uint32_t*)&p1;
            *(uint2*)(bs + base) = u;
        }
    }
}

// ============ fused attention: scores + softmax + PV ============
#define PQ 72     // bf16 tile pitch (elems)
#define PS 132    // fp32 Sbuf pitch
#define PP 136    // bf16 Pbf pitch
#define SO_QHI 0
#define SO_QLO (SO_QHI + 128*PQ*2)
#define SO_KHI (SO_QLO + 128*PQ*2)
#define SO_KLO (SO_KHI + 128*PQ*2)
#define SO_VB  (SO_KLO + 128*PQ*2)
#define SO_SB  (SO_VB  + 128*PQ*2)            // Sbuf (pass1) / Pbf (pass2) union
#define FUSED_SMEM (SO_SB + 128*PS*4)         // 159744 bytes

__device__ __forceinline__ void ld_tile_bf(__nv_bfloat16* dst, const __nv_bfloat16* src, int tid)
{
    #pragma unroll
    for (int i = 0; i < 4; i++) {
        int idx = tid + i * 256;
        int r = idx >> 3, c8 = (idx & 7) * 8;
        uint4 v = *(const uint4*)(src + (size_t)r * HID + c8);
        *(uint4*)(dst + r * PQ + c8) = v;
    }
}

__global__ __launch_bounds__(256)
void attn_fused(float* __restrict__ probs)
{
    extern __shared__ char sm[];
    __nv_bfloat16* Qhi = (__nv_bfloat16*)(sm + SO_QHI);
    __nv_bfloat16* Qlo = (__nv_bfloat16*)(sm + SO_QLO);
    __nv_bfloat16* Khi = (__nv_bfloat16*)(sm + SO_KHI);
    __nv_bfloat16* Klo = (__nv_bfloat16*)(sm + SO_KLO);
    __nv_bfloat16* Vb  = (__nv_bfloat16*)(sm + SO_VB);
    float*         Sbuf = (float*)(sm + SO_SB);
    __nv_bfloat16* Pbf  = (__nv_bfloat16*)(sm + SO_SB);

    const int tid = threadIdx.x, wid = tid >> 5;
    const int bh = blockIdx.y;
    const int b = bh / NHEAD, h = bh % NHEAD;
    const int s0 = blockIdx.x * 128;
    const int wm = wid & 3, wn = wid >> 2;

    const size_t qb = (size_t)(b * SEQ + s0) * HID + h * HDIM;
    const size_t kvb = (size_t)b * SEQ * HID + h * HDIM;

    ld_tile_bf(Qhi, g_qhi + qb, tid);
    ld_tile_bf(Qlo, g_qlo + qb, tid);

    // per-row softmax state: thread pair (2r, 2r+1) owns row r; state replicated in both
    const int row = tid >> 1, colb = (tid & 1) * 64;
    float* srow = probs + ((size_t)bh * SEQ + s0 + row) * SEQ + colb;
    float m_run = -1e30f, sum_run = 0.f;

    // ---------------- pass 1: scores MMA + raw store + online max/sum ----------------
    for (int j = 0; j < 16; j++) {
        const int t0 = j * 128;
        ld_tile_bf(Khi, g_khi + kvb + (size_t)t0 * HID, tid);
        ld_tile_bf(Klo, g_klo + kvb + (size_t)t0 * HID, tid);
        __syncthreads();

        wmma::fragment<wmma::accumulator, 16, 16, 16, float> acc[2][4];
        #pragma unroll
        for (int i = 0; i < 2; i++)
            #pragma unroll
            for (int jj = 0; jj < 4; jj++)
                wmma::fill_fragment(acc[i][jj], 0.f);

        #pragma unroll
        for (int pass = 0; pass < 3; pass++) {
            const __nv_bfloat16* A = (pass == 2) ? Qlo : Qhi;
            const __nv_bfloat16* B = (pass == 1) ? Klo : Khi;
            #pragma unroll
            for (int k0 = 0; k0 < HDIM; k0 += 16) {
                wmma::fragment<wmma::matrix_a, 16, 16, 16, __nv_bfloat16, wmma::row_major> af[2];
                wmma::fragment<wmma::matrix_b, 16, 16, 16, __nv_bfloat16, wmma::col_major> bf[4];
                #pragma unroll
                for (int i = 0; i < 2; i++)
                    wmma::load_matrix_sync(af[i], A + (wm * 32 + i * 16) * PQ + k0, PQ);
                #pragma unroll
                for (int jj = 0; jj < 4; jj++)
                    wmma::load_matrix_sync(bf[jj], B + (wn * 64 + jj * 16) * PQ + k0, PQ);
                #pragma unroll
                for (int i = 0; i < 2; i++)
                    #pragma unroll
                    for (int jj = 0; jj < 4; jj++)
                        wmma::mma_sync(acc[i][jj], af[i], bf[jj], acc[i][jj]);
            }
        }
        #pragma unroll
        for (int i = 0; i < 2; i++)
            #pragma unroll
            for (int jj = 0; jj < 4; jj++)
                wmma::store_matrix_sync(Sbuf + (wm * 32 + i * 16) * PS + wn * 64 + jj * 16,
                                        acc[i][jj], PS, wmma::mem_row_major);
        __syncthreads();

        // raw store to gmem + online (max, sum)
        const float* sr = Sbuf + row * PS + colb;
        float lmax = -1e30f;
        #pragma unroll
        for (int c = 0; c < 64; c += 4) {
            float4 v = *(const float4*)(sr + c);
            *(float4*)(srow + t0 + c) = v;
            lmax = fmaxf(lmax, fmaxf(fmaxf(v.x, v.y), fmaxf(v.z, v.w)));
        }
        lmax = fmaxf(lmax, __shfl_xor_sync(0xffffffffu, lmax, 1));
        float m_new = fmaxf(m_run, lmax);
        float lsum = 0.f;
        #pragma unroll
        for (int c = 0; c < 64; c += 4) {
            float4 v = *(const float4*)(sr + c);
            lsum += __expf(v.x - m_new) + __expf(v.y - m_new)
                  + __expf(v.z - m_new) + __expf(v.w - m_new);
        }
        lsum += __shfl_xor_sync(0xffffffffu, lsum, 1);
        sum_run = sum_run * __expf(m_run - m_new) + lsum;
        m_run = m_new;
        __syncthreads();
    }
    const float inv_sum = 1.f / sum_run;

    // ---------------- pass 2: normalize + write probs + PV MMA ----------------
    wmma::fragment<wmma::accumulator, 16, 16, 16, float> cacc[2][2];
    #pragma unroll
    for (int i = 0; i < 2; i++)
        #pragma unroll
        for (int jj = 0; jj < 2; jj++)
            wmma::fill_fragment(cacc[i][jj], 0.f);

    for (int j = 0; j < 16; j++) {
        const int t0 = j * 128;
        ld_tile_bf(Vb, g_vb + kvb + (size_t)t0 * HID, tid);

        // re-read own raw scores (program order per thread), normalize, write, stash bf16
        #pragma unroll
        for (int c = 0; c < 64; c += 4) {
            float4 v = *(const float4*)(srow + t0 + c);
            float4 p;
            p.x = __expf(v.x - m_run) * inv_sum;
            p.y = __expf(v.y - m_run) * inv_sum;
            p.z = __expf(v.z - m_run) * inv_sum;
            p.w = __expf(v.w - m_run) * inv_sum;
            *(float4*)(srow + t0 + c) = p;
            __nv_bfloat162 b0 = __floats2bfloat162_rn(p.x, p.y);
            __nv_bfloat162 b1 = __floats2bfloat162_rn(p.z, p.w);
            uint2 u;
            u.x = *(uint32_t*)&b0; u.y = *(uint32_t*)&b1;
            *(uint2*)(Pbf + row * PP + colb + c) = u;
        }
        __syncthreads();

        #pragma unroll
        for (int k0 = 0; k0 < 128; k0 += 16) {
            wmma::fragment<wmma::matrix_a, 16, 16, 16, __nv_bfloat16, wmma::row_major> af[2];
            wmma::fragment<wmma::matrix_b, 16, 16, 16, __nv_bfloat16, wmma::row_major> bf[2];
            #pragma unroll
            for (int i = 0; i < 2; i++)
                wmma::load_matrix_sync(af[i], Pbf + (wm * 32 + i * 16) * PP + k0, PP);
            #pragma unroll
            for (int jj = 0; jj < 2; jj++)
                wmma::load_matrix_sync(bf[jj], Vb + k0 * PQ + wn * 32 + jj * 16, PQ);
            #pragma unroll
            for (int i = 0; i < 2; i++)
                #pragma unroll
                for (int jj = 0; jj < 2; jj++)
                    wmma::mma_sync(cacc[i][jj], af[i], bf[jj], cacc[i][jj]);
        }
        __syncthreads();
    }

    #pragma unroll
    for (int i = 0; i < 2; i++)
        #pragma unroll
        for (int jj = 0; jj < 2; jj++) {
            float* op = g_ctx + (size_t)(b * SEQ + s0 + wm * 32 + i * 16) * HID
                        + h * HDIM + wn * 32 + jj * 16;
            wmma::store_matrix_sync(op, cacc[i][jj], HID, wmma::mem_row_major);
        }
}

// ============ 'nowb' LayerNorm ============
__global__ __launch_bounds__(256)
void ln_kernel(const float* __restrict__ y, float* __restrict__ out)
{
    const float* yr = y + (size_t)blockIdx.x * HID;
    float* orow = out + (size_t)blockIdx.x * HID;
    const int tid = threadIdx.x;
    __shared__ float sh[8];

    float v[3];
    float sum = 0.f;
    #pragma unroll
    for (int i = 0; i < 3; i++) { v[i] = yr[tid + i * 256]; sum += v[i]; }
    #pragma unroll
    for (int o = 16; o; o >>= 1) sum += __shfl_xor_sync(0xffffffffu, sum, o);
    if ((tid & 31) == 0) sh[tid >> 5] = sum;
    __syncthreads();
    sum = 0.f;
    #pragma unroll
    for (int i = 0; i < 8; i++) sum += sh[i];
    float mean = sum * (1.f / HID);
    __syncthreads();

    float ss = 0.f;
    #pragma unroll
    for (int i = 0; i < 3; i++) { float d = v[i] - mean; ss += d * d; }
    #pragma unroll
    for (int o = 16; o; o >>= 1) ss += __shfl_xor_sync(0xffffffffu, ss, o);
    if ((tid & 31) == 0) sh[tid >> 5] = ss;
    __syncthreads();
    ss = 0.f;
    #pragma unroll
    for (int i = 0; i < 8; i++) ss += sh[i];
    float stdv = sqrtf(ss * (1.f / (HID - 1)));
    float inv = 1.f / (stdv + LNEPS);
    #pragma unroll
    for (int i = 0; i < 3; i++) orow[tid + i * 256] = (v[i] - mean) * inv;
}

// ---------------- launch ----------------
extern "C" void kernel_launch(void* const* d_in, const int* in_sizes, int n_in,
                              void* d_out, int out_size)
{
    const float* x  = (const float*)d_in[0];
    const float* Wq = (const float*)d_in[1];
    const float* bq = (const float*)d_in[2];
    const float* Wk = (const float*)d_in[3];
    const float* bk = (const float*)d_in[4];
    const float* Wv = (const float*)d_in[5];
    const float* bv = (const float*)d_in[6];
    const float* Wo = (const float*)d_in[7];
    const float* bo = (const float*)d_in[8];

    float* out   = (float*)d_out;
    float* probs = out + (size_t)MTOK * HID;

    float *ctx, *y;
    __nv_bfloat16 *qhi, *qlo, *khi, *klo, *vb;
    cudaGetSymbolAddress((void**)&ctx, g_ctx);
    cudaGetSymbolAddress((void**)&y,   g_y);
    cudaGetSymbolAddress((void**)&qhi, g_qhi);
    cudaGetSymbolAddress((void**)&qlo, g_qlo);
    cudaGetSymbolAddress((void**)&khi, g_khi);
    cudaGetSymbolAddress((void**)&klo, g_klo);
    cudaGetSymbolAddress((void**)&vb,  g_vb);

    cudaFuncSetAttribute(attn_fused, cudaFuncAttributeMaxDynamicSharedMemorySize, FUSED_SMEM);

    dim3 gproj(MTOK / 128, HID / 64);
    proj_gemm<<<gproj, 256>>>(x, Wq, bq, nullptr, nullptr, qhi, qlo, nullptr, 0);
    proj_gemm<<<gproj, 256>>>(x, Wk, bk, nullptr, nullptr, khi, klo, nullptr, 0);
    proj_gemm<<<gproj, 256>>>(x, Wv, bv, nullptr, nullptr, nullptr, nullptr, vb, 0);

    attn_fused<<<dim3(SEQ / 128, BATCH * NHEAD), 256, FUSED_SMEM>>>(probs);

    proj_gemm<<<gproj, 256>>>(ctx, Wo, bo, x, y, nullptr, nullptr, nullptr, 1);

    ln_kernel<<<MTOK, 256>>>(y, out);
}

// round 7
// speedup vs baseline: 1.2528x; 1.2528x over previous
#include <cuda_runtime.h>
#include <cuda_bf16.h>
#include <mma.h>
#include <cstdint>

using namespace nvcuda;

#define BATCH 2
#define SEQ   2048
#define HID   768
#define NHEAD 12
#define HDIM  64
#define MTOK  (BATCH*SEQ)
#define GAMMA 0.05f
#define LNEPS 1e-12f
#define SPAD  88

typedef unsigned long long u64;

__device__ __forceinline__ void fma2(u64& d, u64 a, u64 b) {
    asm("fma.rn.f32x2 %0, %1, %2, %0;" : "+l"(d) : "l"(a), "l"(b));
}
__device__ __forceinline__ u64 dup2(float x) {
    u64 r; asm("mov.b64 %0, {%1, %1};" : "=l"(r) : "f"(x)); return r;
}
__device__ __forceinline__ float2 unpk2(u64 v) {
    float2 r; asm("mov.b64 {%0, %1}, %2;" : "=f"(r.x), "=f"(r.y) : "l"(v)); return r;
}

// ---------------- scratch ----------------
__device__ __nv_bfloat16 g_qhi[MTOK*HID];
__device__ __nv_bfloat16 g_qlo[MTOK*HID];
__device__ __nv_bfloat16 g_khi[MTOK*HID];
__device__ __nv_bfloat16 g_klo[MTOK*HID];
__device__ __nv_bfloat16 g_vb [MTOK*HID];
__device__ __nv_bfloat16 g_pbf[(size_t)BATCH*NHEAD*SEQ*SEQ];
__device__ float g_ctx[MTOK*HID];
__device__ float g_y[MTOK*HID];

// ============ projection GEMM: C = A @ W^T + bias (+res) ============
__global__ __launch_bounds__(256, 2)
void proj_gemm(const float* __restrict__ A, const float* __restrict__ W,
               const float* __restrict__ bias, const float* __restrict__ res,
               float* __restrict__ C,
               __nv_bfloat16* __restrict__ hi, __nv_bfloat16* __restrict__ lo,
               __nv_bfloat16* __restrict__ bs,
               int gamma_mode)
{
    __shared__ float As[32][132];
    __shared__ float Ws[32][68];
    const int tid = threadIdx.x;
    const int tx = tid & 15, ty = tid >> 4;
    const int bm = blockIdx.x * 128;
    const int bn = blockIdx.y * 64;
    u64 acc2[8][2] = {};

    const float* Abase = A + (size_t)bm * HID;
    const float* Wbase = W + (size_t)bn * HID;

    for (int k0 = 0; k0 < HID; k0 += 32) {
        #pragma unroll
        for (int i = 0; i < 4; i++) {
            int f4 = tid + i * 256;
            int m = f4 >> 3, kk = (f4 & 7) * 4;
            float4 v = *(const float4*)(Abase + (size_t)m * HID + k0 + kk);
            As[kk + 0][m] = v.x; As[kk + 1][m] = v.y;
            As[kk + 2][m] = v.z; As[kk + 3][m] = v.w;
        }
        #pragma unroll
        for (int i = 0; i < 2; i++) {
            int f4 = tid + i * 256;
            int n = f4 >> 3, kk = (f4 & 7) * 4;
            float4 v = *(const float4*)(Wbase + (size_t)n * HID + k0 + kk);
            if (gamma_mode) {
                v.x += GAMMA * fmaxf(v.x, 0.f); v.y += GAMMA * fmaxf(v.y, 0.f);
                v.z += GAMMA * fmaxf(v.z, 0.f); v.w += GAMMA * fmaxf(v.w, 0.f);
            }
            Ws[kk + 0][n] = v.x; Ws[kk + 1][n] = v.y;
            Ws[kk + 2][n] = v.z; Ws[kk + 3][n] = v.w;
        }
        __syncthreads();
        #pragma unroll
        for (int k = 0; k < 32; k++) {
            float4 a0 = *(const float4*)&As[k][ty * 8];
            float4 a1 = *(const float4*)&As[k][ty * 8 + 4];
            ulonglong2 wp = *(const ulonglong2*)&Ws[k][tx * 4];
            float a[8] = {a0.x, a0.y, a0.z, a0.w, a1.x, a1.y, a1.z, a1.w};
            #pragma unroll
            for (int i = 0; i < 8; i++) {
                u64 ad = dup2(a[i]);
                fma2(acc2[i][0], ad, wp.x);
                fma2(acc2[i][1], ad, wp.y);
            }
        }
        __syncthreads();
    }

    float4 b = *(const float4*)(bias + bn + tx * 4);
    if (gamma_mode) {
        b.x += GAMMA * fmaxf(b.x, 0.f); b.y += GAMMA * fmaxf(b.y, 0.f);
        b.z += GAMMA * fmaxf(b.z, 0.f); b.w += GAMMA * fmaxf(b.w, 0.f);
    }
    #pragma unroll
    for (int i = 0; i < 8; i++) {
        int m = bm + ty * 8 + i;
        size_t base = (size_t)m * HID + bn + tx * 4;
        float2 c0 = unpk2(acc2[i][0]), c1 = unpk2(acc2[i][1]);
        float4 o;
        o.x = c0.x + b.x; o.y = c0.y + b.y;
        o.z = c1.x + b.z; o.w = c1.y + b.w;
        if (res) {
            float4 r = *(const float4*)(res + base);
            o.x += r.x; o.y += r.y; o.z += r.z; o.w += r.w;
        }
        if (C) *(float4*)(C + base) = o;
        if (hi) {
            __nv_bfloat16 h0 = __float2bfloat16(o.x), h1 = __float2bfloat16(o.y);
            __nv_bfloat16 h2 = __float2bfloat16(o.z), h3 = __float2bfloat16(o.w);
            __nv_bfloat16 l0 = __float2bfloat16(o.x - __bfloat162float(h0));
            __nv_bfloat16 l1 = __float2bfloat16(o.y - __bfloat162float(h1));
            __nv_bfloat16 l2 = __float2bfloat16(o.z - __bfloat162float(h2));
            __nv_bfloat16 l3 = __float2bfloat16(o.w - __bfloat162float(h3));
            __nv_bfloat162 hp0 = __halves2bfloat162(h0, h1), hp1 = __halves2bfloat162(h2, h3);
            __nv_bfloat162 lp0 = __halves2bfloat162(l0, l1), lp1 = __halves2bfloat162(l2, l3);
            uint2 hu, lu;
            hu.x = *(uint32_t*)&hp0; hu.y = *(uint32_t*)&hp1;
            lu.x = *(uint32_t*)&lp0; lu.y = *(uint32_t*)&lp1;
            *(uint2*)(hi + base) = hu;
            *(uint2*)(lo + base) = lu;
        }
        if (bs) {
            __nv_bfloat162 p0 = __floats2bfloat162_rn(o.x, o.y);
            __nv_bfloat162 p1 = __floats2bfloat162_rn(o.z, o.w);
            uint2 u;
            u.x = *(uint32_t*)&p0; u.y = *(uint32_t*)&p1;
            *(uint2*)(bs + base) = u;
        }
    }
}

// ============ scores via WMMA bf16 3-pass, 512 threads, 32x32/warp ============
#define SC_TILE (128 * SPAD)
#define SC_SMEM (4 * SC_TILE * 2)

__device__ __forceinline__ void ld_tile512(__nv_bfloat16* dst, const __nv_bfloat16* src, int tid)
{
    #pragma unroll
    for (int i = 0; i < 2; i++) {
        int idx = tid + i * 512;
        int r = idx >> 3, c8 = (idx & 7) * 8;
        uint4 v = *(const uint4*)(src + (size_t)r * HID + c8);
        *(uint4*)(dst + r * SPAD + c8) = v;
    }
}

__global__ __launch_bounds__(512)
void scores_mma(float* __restrict__ probs)
{
    extern __shared__ __nv_bfloat16 sm[];
    __nv_bfloat16* Qhi = sm;
    __nv_bfloat16* Qlo = sm + SC_TILE;
    __nv_bfloat16* Khi = sm + 2 * SC_TILE;
    __nv_bfloat16* Klo = sm + 3 * SC_TILE;

    const int tid = threadIdx.x, wid = tid >> 5;
    const int bh = blockIdx.z;
    const int b = bh / NHEAD, h = bh % NHEAD;
    const int s0 = blockIdx.x * 128;
    const int t0 = blockIdx.y * 128;

    const size_t qb = (size_t)(b * SEQ + s0) * HID + h * HDIM;
    const size_t kb = (size_t)(b * SEQ + t0) * HID + h * HDIM;
    ld_tile512(Qhi, g_qhi + qb, tid);
    ld_tile512(Qlo, g_qlo + qb, tid);
    ld_tile512(Khi, g_khi + kb, tid);
    ld_tile512(Klo, g_klo + kb, tid);
    __syncthreads();

    const int wm = wid & 3;       // 4 m-warps x 32 rows
    const int wn = wid >> 2;      // 4 n-warps x 32 cols

    wmma::fragment<wmma::accumulator, 16, 16, 16, float> acc[2][2];
    #pragma unroll
    for (int i = 0; i < 2; i++)
        #pragma unroll
        for (int j = 0; j < 2; j++)
            wmma::fill_fragment(acc[i][j], 0.f);

    #pragma unroll
    for (int pass = 0; pass < 3; pass++) {
        const __nv_bfloat16* A = (pass == 2) ? Qlo : Qhi;
        const __nv_bfloat16* B = (pass == 1) ? Klo : Khi;
        #pragma unroll
        for (int k0 = 0; k0 < HDIM; k0 += 16) {
            wmma::fragment<wmma::matrix_a, 16, 16, 16, __nv_bfloat16, wmma::row_major> af[2];
            wmma::fragment<wmma::matrix_b, 16, 16, 16, __nv_bfloat16, wmma::col_major> bf[2];
            #pragma unroll
            for (int i = 0; i < 2; i++)
                wmma::load_matrix_sync(af[i], A + (wm * 32 + i * 16) * SPAD + k0, SPAD);
            #pragma unroll
            for (int j = 0; j < 2; j++)
                wmma::load_matrix_sync(bf[j], B + (wn * 32 + j * 16) * SPAD + k0, SPAD);
            #pragma unroll
            for (int i = 0; i < 2; i++)
                #pragma unroll
                for (int j = 0; j < 2; j++)
                    wmma::mma_sync(acc[i][j], af[i], bf[j], acc[i][j]);
        }
    }

    #pragma unroll
    for (int i = 0; i < 2; i++)
        #pragma unroll
        for (int j = 0; j < 2; j++) {
            float* op = probs + ((size_t)bh * SEQ + s0 + wm * 32 + i * 16) * SEQ
                        + t0 + wn * 32 + j * 16;
            wmma::store_matrix_sync(op, acc[i][j], SEQ, wmma::mem_row_major);
        }
}

// ============ softmax: fp32 in-place + bf16 copy for PV ============
__global__ __launch_bounds__(256)
void softmax_kernel(float* __restrict__ probs, __nv_bfloat16* __restrict__ pbf)
{
    float* p = probs + (size_t)blockIdx.x * SEQ;
    __nv_bfloat16* pb = pbf + (size_t)blockIdx.x * SEQ;
    const int tid = threadIdx.x;
    __shared__ float sh[8];

    float4 v[2];
    v[0] = *(const float4*)(p + tid * 8);
    v[1] = *(const float4*)(p + tid * 8 + 4);
    float mx = fmaxf(fmaxf(fmaxf(v[0].x, v[0].y), fmaxf(v[0].z, v[0].w)),
                     fmaxf(fmaxf(v[1].x, v[1].y), fmaxf(v[1].z, v[1].w)));
    #pragma unroll
    for (int o = 16; o; o >>= 1) mx = fmaxf(mx, __shfl_xor_sync(0xffffffffu, mx, o));
    if ((tid & 31) == 0) sh[tid >> 5] = mx;
    __syncthreads();
    mx = sh[0];
    #pragma unroll
    for (int i = 1; i < 8; i++) mx = fmaxf(mx, sh[i]);
    __syncthreads();

    float sum = 0.f;
    #pragma unroll
    for (int i = 0; i < 2; i++) {
        v[i].x = __expf(v[i].x - mx); v[i].y = __expf(v[i].y - mx);
        v[i].z = __expf(v[i].z - mx); v[i].w = __expf(v[i].w - mx);
        sum += (v[i].x + v[i].y) + (v[i].z + v[i].w);
    }
    #pragma unroll
    for (int o = 16; o; o >>= 1) sum += __shfl_xor_sync(0xffffffffu, sum, o);
    if ((tid & 31) == 0) sh[tid >> 5] = sum;
    __syncthreads();
    sum = 0.f;
    #pragma unroll
    for (int i = 0; i < 8; i++) sum += sh[i];
    float inv = 1.f / sum;
    #pragma unroll
    for (int i = 0; i < 2; i++) {
        v[i].x *= inv; v[i].y *= inv; v[i].z *= inv; v[i].w *= inv;
    }
    *(float4*)(p + tid * 8) = v[0];
    *(float4*)(p + tid * 8 + 4) = v[1];

    __nv_bfloat162 b0 = __floats2bfloat162_rn(v[0].x, v[0].y);
    __nv_bfloat162 b1 = __floats2bfloat162_rn(v[0].z, v[0].w);
    __nv_bfloat162 b2 = __floats2bfloat162_rn(v[1].x, v[1].y);
    __nv_bfloat162 b3 = __floats2bfloat162_rn(v[1].z, v[1].w);
    uint4 u;
    u.x = *(uint32_t*)&b0; u.y = *(uint32_t*)&b1;
    u.z = *(uint32_t*)&b2; u.w = *(uint32_t*)&b3;
    *(uint4*)(pb + tid * 8) = u;
}

// ============ ctx = P @ V via WMMA bf16, 2 CTAs/SM ============
__global__ __launch_bounds__(256, 2)
void pv_mma()
{
    __shared__ __nv_bfloat16 Pb[128 * SPAD];
    __shared__ __nv_bfloat16 Vb[64 * SPAD];
    const int tid = threadIdx.x, wid = tid >> 5;
    const int bh = blockIdx.y;
    const int b = bh / NHEAD, h = bh % NHEAD;
    const int s0 = blockIdx.x * 128;

    const __nv_bfloat16* pbase = g_pbf + ((size_t)bh * SEQ + s0) * SEQ;
    const __nv_bfloat16* vbase = g_vb + (size_t)b * SEQ * HID + h * HDIM;

    const int wm = wid & 3;
    const int wn = wid >> 2;

    wmma::fragment<wmma::accumulator, 16, 16, 16, float> acc[2][2];
    #pragma unroll
    for (int i = 0; i < 2; i++)
        #pragma unroll
        for (int j = 0; j < 2; j++)
            wmma::fill_fragment(acc[i][j], 0.f);

    for (int t0 = 0; t0 < SEQ; t0 += 64) {
        #pragma unroll
        for (int i = 0; i < 4; i++) {
            int idx = tid + i * 256;
            int r = idx >> 3, c8 = (idx & 7) * 8;
            uint4 v = *(const uint4*)(pbase + (size_t)r * SEQ + t0 + c8);
            *(uint4*)(Pb + r * SPAD + c8) = v;
        }
        #pragma unroll
        for (int i = 0; i < 2; i++) {
            int idx = tid + i * 256;
            int r = idx >> 3, c8 = (idx & 7) * 8;
            uint4 v = *(const uint4*)(vbase + (size_t)(t0 + r) * HID + c8);
            *(uint4*)(Vb + r * SPAD + c8) = v;
        }
        __syncthreads();
        #pragma unroll
        for (int k0 = 0; k0 < 64; k0 += 16) {
            wmma::fragment<wmma::matrix_a, 16, 16, 16, __nv_bfloat16, wmma::row_major> af[2];
            wmma::fragment<wmma::matrix_b, 16, 16, 16, __nv_bfloat16, wmma::row_major> bf[2];
            #pragma unroll
            for (int i = 0; i < 2; i++)
                wmma::load_matrix_sync(af[i], Pb + (wm * 32 + i * 16) * SPAD + k0, SPAD);
            #pragma unroll
            for (int j = 0; j < 2; j++)
                wmma::load_matrix_sync(bf[j], Vb + k0 * SPAD + wn * 32 + j * 16, SPAD);
            #pragma unroll
            for (int i = 0; i < 2; i++)
                #pragma unroll
                for (int j = 0; j < 2; j++)
                    wmma::mma_sync(acc[i][j], af[i], bf[j], acc[i][j]);
        }
        __syncthreads();
    }

    #pragma unroll
    for (int i = 0; i < 2; i++)
        #pragma unroll
        for (int j = 0; j < 2; j++) {
            float* op = g_ctx + (size_t)(b * SEQ + s0 + wm * 32 + i * 16) * HID
                        + h * HDIM + wn * 32 + j * 16;
            wmma::store_matrix_sync(op, acc[i][j], HID, wmma::mem_row_major);
        }
}

// ============ 'nowb' LayerNorm ============
__global__ __launch_bounds__(256)
void ln_kernel(const float* __restrict__ y, float* __restrict__ out)
{
    const float* yr = y + (size_t)blockIdx.x * HID;
    float* orow = out + (size_t)blockIdx.x * HID;
    const int tid = threadIdx.x;
    __shared__ float sh[8];

    float v[3];
    float sum = 0.f;
    #pragma unroll
    for (int i = 0; i < 3; i++) { v[i] = yr[tid + i * 256]; sum += v[i]; }
    #pragma unroll
    for (int o = 16; o; o >>= 1) sum += __shfl_xor_sync(0xffffffffu, sum, o);
    if ((tid & 31) == 0) sh[tid >> 5] = sum;
    __syncthreads();
    sum = 0.f;
    #pragma unroll
    for (int i = 0; i < 8; i++) sum += sh[i];
    float mean = sum * (1.f / HID);
    __syncthreads();

    float ss = 0.f;
    #pragma unroll
    for (int i = 0; i < 3; i++) { float d = v[i] - mean; ss += d * d; }
    #pragma unroll
    for (int o = 16; o; o >>= 1) ss += __shfl_xor_sync(0xffffffffu, ss, o);
    if ((tid & 31) == 0) sh[tid >> 5] = ss;
    __syncthreads();
    ss = 0.f;
    #pragma unroll
    for (int i = 0; i < 8; i++) ss += sh[i];
    float stdv = sqrtf(ss * (1.f / (HID - 1)));
    float inv = 1.f / (stdv + LNEPS);
    #pragma unroll
    for (int i = 0; i < 3; i++) orow[tid + i * 256] = (v[i] - mean) * inv;
}

// ---------------- launch ----------------
extern "C" void kernel_launch(void* const* d_in, const int* in_sizes, int n_in,
                              void* d_out, int out_size)
{
    const float* x  = (const float*)d_in[0];
    const float* Wq = (const float*)d_in[1];
    const float* bq = (const float*)d_in[2];
    const float* Wk = (const float*)d_in[3];
    const float* bk = (const float*)d_in[4];
    const float* Wv = (const float*)d_in[5];
    const float* bv = (const float*)d_in[6];
    const float* Wo = (const float*)d_in[7];
    const float* bo = (const float*)d_in[8];

    float* out   = (float*)d_out;
    float* probs = out + (size_t)MTOK * HID;

    float *ctx, *y;
    __nv_bfloat16 *qhi, *qlo, *khi, *klo, *vb, *pbf;
    cudaGetSymbolAddress((void**)&ctx, g_ctx);
    cudaGetSymbolAddress((void**)&y,   g_y);
    cudaGetSymbolAddress((void**)&qhi, g_qhi);
    cudaGetSymbolAddress((void**)&qlo, g_qlo);
    cudaGetSymbolAddress((void**)&khi, g_khi);
    cudaGetSymbolAddress((void**)&klo, g_klo);
    cudaGetSymbolAddress((void**)&vb,  g_vb);
    cudaGetSymbolAddress((void**)&pbf, g_pbf);

    cudaFuncSetAttribute(scores_mma, cudaFuncAttributeMaxDynamicSharedMemorySize, SC_SMEM);

    dim3 gproj(MTOK / 128, HID / 64);
    proj_gemm<<<gproj, 256>>>(x, Wq, bq, nullptr, nullptr, qhi, qlo, nullptr, 0);
    proj_gemm<<<gproj, 256>>>(x, Wk, bk, nullptr, nullptr, khi, klo, nullptr, 0);
    proj_gemm<<<gproj, 256>>>(x, Wv, bv, nullptr, nullptr, nullptr, nullptr, vb, 0);

    scores_mma<<<dim3(SEQ / 128, SEQ / 128, BATCH * NHEAD), 512, SC_SMEM>>>(probs);

    softmax_kernel<<<BATCH * NHEAD * SEQ, 256>>>(probs, pbf);

    pv_mma<<<dim3(SEQ / 128, BATCH * NHEAD), 256>>>();

    proj_gemm<<<gproj, 256>>>(ctx, Wo, bo, x, y, nullptr, nullptr, nullptr, 1);

    ln_kernel<<<MTOK, 256>>>(y, out);
}

// round 8
// speedup vs baseline: 1.6410x; 1.3099x over previous
#include <cuda_runtime.h>
#include <cuda_bf16.h>
#include <mma.h>
#include <cstdint>

using namespace nvcuda;

#define BATCH 2
#define SEQ   2048
#define HID   768
#define NHEAD 12
#define HDIM  64
#define MTOK  (BATCH*SEQ)
#define GAMMA 0.05f
#define LNEPS 1e-12f
#define SPAD  88
#define WPAD  72      // proj tile pitch (bf16 elems)

typedef unsigned long long u64;

// ---------------- scratch ----------------
__device__ __nv_bfloat16 g_xhi[MTOK*HID];
__device__ __nv_bfloat16 g_xlo[MTOK*HID];
__device__ __nv_bfloat16 g_qhi[MTOK*HID];
__device__ __nv_bfloat16 g_qlo[MTOK*HID];
__device__ __nv_bfloat16 g_khi[MTOK*HID];
__device__ __nv_bfloat16 g_klo[MTOK*HID];
__device__ __nv_bfloat16 g_vb [MTOK*HID];
__device__ __nv_bfloat16 g_pbf[(size_t)BATCH*NHEAD*SEQ*SEQ];
__device__ __nv_bfloat16 g_chi[MTOK*HID];
__device__ __nv_bfloat16 g_clo[MTOK*HID];
__device__ float g_ctx[MTOK*HID];
__device__ float g_y[MTOK*HID];

// ============ fp32 -> bf16 hi/lo split ============
__global__ __launch_bounds__(256)
void cvt_hilo(const float* __restrict__ in, __nv_bfloat16* __restrict__ hi,
              __nv_bfloat16* __restrict__ lo, int n4)
{
    int idx = blockIdx.x * 256 + threadIdx.x;
    if (idx >= n4) return;
    float4 v = ((const float4*)in)[idx];
    __nv_bfloat16 h0 = __float2bfloat16(v.x), h1 = __float2bfloat16(v.y);
    __nv_bfloat16 h2 = __float2bfloat16(v.z), h3 = __float2bfloat16(v.w);
    __nv_bfloat16 l0 = __float2bfloat16(v.x - __bfloat162float(h0));
    __nv_bfloat16 l1 = __float2bfloat16(v.y - __bfloat162float(h1));
    __nv_bfloat16 l2 = __float2bfloat16(v.z - __bfloat162float(h2));
    __nv_bfloat16 l3 = __float2bfloat16(v.w - __bfloat162float(h3));
    __nv_bfloat162 hp0 = __halves2bfloat162(h0, h1), hp1 = __halves2bfloat162(h2, h3);
    __nv_bfloat162 lp0 = __halves2bfloat162(l0, l1), lp1 = __halves2bfloat162(l2, l3);
    uint2 hu, lu;
    hu.x = *(uint32_t*)&hp0; hu.y = *(uint32_t*)&hp1;
    lu.x = *(uint32_t*)&lp0; lu.y = *(uint32_t*)&lp1;
    ((uint2*)hi)[idx] = hu;
    ((uint2*)lo)[idx] = lu;
}

// ============ WMMA projection: C = A @ W^T + bias (+res), 3-pass hi/lo ============
// A given as bf16 hi/lo [M, HID]; W fp32 [HID, HID] row-major (row = out feature).
// Tile 128(M) x 64(N) x 64(K); 256 threads, 8 warps (4m x 2n), 32x32/warp.
#define PJ_AHI 0
#define PJ_ALO (PJ_AHI + 128*WPAD)
#define PJ_WHI (PJ_ALO + 128*WPAD)
#define PJ_WLO (PJ_WHI + 64*WPAD)
#define PJ_ELEMS (PJ_WLO + 64*WPAD)       // 27648 bf16 = 55296 B
#define PJ_SMEM (PJ_ELEMS * 2)

__global__ __launch_bounds__(256, 2)
void proj_wmma(const __nv_bfloat16* __restrict__ Ahi, const __nv_bfloat16* __restrict__ Alo,
               const float* __restrict__ W, const float* __restrict__ bias,
               const float* __restrict__ res,
               float* __restrict__ C,
               __nv_bfloat16* __restrict__ hi, __nv_bfloat16* __restrict__ lo,
               __nv_bfloat16* __restrict__ bs,
               int gamma_mode)
{
    extern __shared__ __nv_bfloat16 sm[];
    __nv_bfloat16* Ahi_s = sm + PJ_AHI;
    __nv_bfloat16* Alo_s = sm + PJ_ALO;
    __nv_bfloat16* Whi_s = sm + PJ_WHI;
    __nv_bfloat16* Wlo_s = sm + PJ_WLO;
    float* scr = (float*)sm;              // epilogue scratch overlays tiles (34.8KB <= 54KB)

    const int tid = threadIdx.x, wid = tid >> 5;
    const int bm = blockIdx.x * 128;
    const int bn = blockIdx.y * 64;
    const int wm = wid & 3, wn = wid >> 2;

    wmma::fragment<wmma::accumulator, 16, 16, 16, float> acc[2][2];
    #pragma unroll
    for (int i = 0; i < 2; i++)
        #pragma unroll
        for (int j = 0; j < 2; j++)
            wmma::fill_fragment(acc[i][j], 0.f);

    for (int k0 = 0; k0 < HID; k0 += 64) {
        // A hi/lo tiles: 128 x 64 bf16, 4 uint4 per thread each
        #pragma unroll
        for (int i = 0; i < 4; i++) {
            int idx = tid + i * 256;
            int r = idx >> 3, c8 = (idx & 7) * 8;
            size_t go = (size_t)(bm + r) * HID + k0 + c8;
            *(uint4*)(Ahi_s + r * WPAD + c8) = *(const uint4*)(Ahi + go);
            *(uint4*)(Alo_s + r * WPAD + c8) = *(const uint4*)(Alo + go);
        }
        // W tile: 64 n x 64 k fp32 -> gamma -> hi/lo bf16
        #pragma unroll
        for (int i = 0; i < 4; i++) {
            int idx = tid + i * 256;
            int n = idx >> 4, kf = (idx & 15) * 4;
            float4 w = *(const float4*)(W + (size_t)(bn + n) * HID + k0 + kf);
            if (gamma_mode) {
                w.x += GAMMA * fmaxf(w.x, 0.f); w.y += GAMMA * fmaxf(w.y, 0.f);
                w.z += GAMMA * fmaxf(w.z, 0.f); w.w += GAMMA * fmaxf(w.w, 0.f);
            }
            __nv_bfloat16 h0 = __float2bfloat16(w.x), h1 = __float2bfloat16(w.y);
            __nv_bfloat16 h2 = __float2bfloat16(w.z), h3 = __float2bfloat16(w.w);
            __nv_bfloat16 l0 = __float2bfloat16(w.x - __bfloat162float(h0));
            __nv_bfloat16 l1 = __float2bfloat16(w.y - __bfloat162float(h1));
            __nv_bfloat16 l2 = __float2bfloat16(w.z - __bfloat162float(h2));
            __nv_bfloat16 l3 = __float2bfloat16(w.w - __bfloat162float(h3));
            __nv_bfloat162 hp0 = __halves2bfloat162(h0, h1), hp1 = __halves2bfloat162(h2, h3);
            __nv_bfloat162 lp0 = __halves2bfloat162(l0, l1), lp1 = __halves2bfloat162(l2, l3);
            uint2 hu, lu;
            hu.x = *(uint32_t*)&hp0; hu.y = *(uint32_t*)&hp1;
            lu.x = *(uint32_t*)&lp0; lu.y = *(uint32_t*)&lp1;
            *(uint2*)(Whi_s + n * WPAD + kf) = hu;
            *(uint2*)(Wlo_s + n * WPAD + kf) = lu;
        }
        __syncthreads();

        #pragma unroll
        for (int pass = 0; pass < 3; pass++) {
            const __nv_bfloat16* A = (pass == 2) ? Alo_s : Ahi_s;
            const __nv_bfloat16* B = (pass == 1) ? Wlo_s : Whi_s;
            #pragma unroll
            for (int ks = 0; ks < 64; ks += 16) {
                wmma::fragment<wmma::matrix_a, 16, 16, 16, __nv_bfloat16, wmma::row_major> af[2];
                wmma::fragment<wmma::matrix_b, 16, 16, 16, __nv_bfloat16, wmma::col_major> bf[2];
                #pragma unroll
                for (int i = 0; i < 2; i++)
                    wmma::load_matrix_sync(af[i], A + (wm * 32 + i * 16) * WPAD + ks, WPAD);
                #pragma unroll
                for (int j = 0; j < 2; j++)
                    wmma::load_matrix_sync(bf[j], B + (wn * 32 + j * 16) * WPAD + ks, WPAD);
                #pragma unroll
                for (int i = 0; i < 2; i++)
                    #pragma unroll
                    for (int j = 0; j < 2; j++)
                        wmma::mma_sync(acc[i][j], af[i], bf[j], acc[i][j]);
            }
        }
        __syncthreads();
    }

    // epilogue: fragments -> scratch -> bias/res/format
    #pragma unroll
    for (int i = 0; i < 2; i++)
        #pragma unroll
        for (int j = 0; j < 2; j++)
            wmma::store_matrix_sync(scr + (wm * 32 + i * 16) * 68 + wn * 32 + j * 16,
                                    acc[i][j], 68, wmma::mem_row_major);
    __syncthreads();

    const int row = tid >> 1, colb = (tid & 1) * 32;
    const int m = bm + row;
    #pragma unroll
    for (int c = 0; c < 32; c += 4) {
        int n = bn + colb + c;
        float4 v = *(const float4*)(scr + row * 68 + colb + c);
        float4 b = *(const float4*)(bias + n);
        if (gamma_mode) {
            b.x += GAMMA * fmaxf(b.x, 0.f); b.y += GAMMA * fmaxf(b.y, 0.f);
            b.z += GAMMA * fmaxf(b.z, 0.f); b.w += GAMMA * fmaxf(b.w, 0.f);
        }
        v.x += b.x; v.y += b.y; v.z += b.z; v.w += b.w;
        size_t base = (size_t)m * HID + n;
        if (res) {
            float4 r = *(const float4*)(res + base);
            v.x += r.x; v.y += r.y; v.z += r.z; v.w += r.w;
        }
        if (C) *(float4*)(C + base) = v;
        if (hi) {
            __nv_bfloat16 h0 = __float2bfloat16(v.x), h1 = __float2bfloat16(v.y);
            __nv_bfloat16 h2 = __float2bfloat16(v.z), h3 = __float2bfloat16(v.w);
            __nv_bfloat16 l0 = __float2bfloat16(v.x - __bfloat162float(h0));
            __nv_bfloat16 l1 = __float2bfloat16(v.y - __bfloat162float(h1));
            __nv_bfloat16 l2 = __float2bfloat16(v.z - __bfloat162float(h2));
            __nv_bfloat16 l3 = __float2bfloat16(v.w - __bfloat162float(h3));
            __nv_bfloat162 hp0 = __halves2bfloat162(h0, h1), hp1 = __halves2bfloat162(h2, h3);
            __nv_bfloat162 lp0 = __halves2bfloat162(l0, l1), lp1 = __halves2bfloat162(l2, l3);
            uint2 hu, lu;
            hu.x = *(uint32_t*)&hp0; hu.y = *(uint32_t*)&hp1;
            lu.x = *(uint32_t*)&lp0; lu.y = *(uint32_t*)&lp1;
            *(uint2*)(hi + base) = hu;
            *(uint2*)(lo + base) = lu;
        }
        if (bs) {
            __nv_bfloat162 p0 = __floats2bfloat162_rn(v.x, v.y);
            __nv_bfloat162 p1 = __floats2bfloat162_rn(v.z, v.w);
            uint2 u;
            u.x = *(uint32_t*)&p0; u.y = *(uint32_t*)&p1;
            *(uint2*)(bs + base) = u;
        }
    }
}

// ============ scores via WMMA bf16 3-pass, 512 threads ============
#define SC_TILE (128 * SPAD)
#define SC_SMEM (4 * SC_TILE * 2)

__device__ __forceinline__ void ld_tile512(__nv_bfloat16* dst, const __nv_bfloat16* src, int tid)
{
    #pragma unroll
    for (int i = 0; i < 2; i++) {
        int idx = tid + i * 512;
        int r = idx >> 3, c8 = (idx & 7) * 8;
        uint4 v = *(const uint4*)(src + (size_t)r * HID + c8);
        *(uint4*)(dst + r * SPAD + c8) = v;
    }
}

__global__ __launch_bounds__(512)
void scores_mma(float* __restrict__ probs)
{
    extern __shared__ __nv_bfloat16 sm[];
    __nv_bfloat16* Qhi = sm;
    __nv_bfloat16* Qlo = sm + SC_TILE;
    __nv_bfloat16* Khi = sm + 2 * SC_TILE;
    __nv_bfloat16* Klo = sm + 3 * SC_TILE;

    const int tid = threadIdx.x, wid = tid >> 5;
    const int bh = blockIdx.z;
    const int b = bh / NHEAD, h = bh % NHEAD;
    const int s0 = blockIdx.x * 128;
    const int t0 = blockIdx.y * 128;

    const size_t qb = (size_t)(b * SEQ + s0) * HID + h * HDIM;
    const size_t kb = (size_t)(b * SEQ + t0) * HID + h * HDIM;
    ld_tile512(Qhi, g_qhi + qb, tid);
    ld_tile512(Qlo, g_qlo + qb, tid);
    ld_tile512(Khi, g_khi + kb, tid);
    ld_tile512(Klo, g_klo + kb, tid);
    __syncthreads();

    const int wm = wid & 3;
    const int wn = wid >> 2;

    wmma::fragment<wmma::accumulator, 16, 16, 16, float> acc[2][2];
    #pragma unroll
    for (int i = 0; i < 2; i++)
        #pragma unroll
        for (int j = 0; j < 2; j++)
            wmma::fill_fragment(acc[i][j], 0.f);

    #pragma unroll
    for (int pass = 0; pass < 3; pass++) {
        const __nv_bfloat16* A = (pass == 2) ? Qlo : Qhi;
        const __nv_bfloat16* B = (pass == 1) ? Klo : Khi;
        #pragma unroll
        for (int k0 = 0; k0 < HDIM; k0 += 16) {
            wmma::fragment<wmma::matrix_a, 16, 16, 16, __nv_bfloat16, wmma::row_major> af[2];
            wmma::fragment<wmma::matrix_b, 16, 16, 16, __nv_bfloat16, wmma::col_major> bf[2];
            #pragma unroll
            for (int i = 0; i < 2; i++)
                wmma::load_matrix_sync(af[i], A + (wm * 32 + i * 16) * SPAD + k0, SPAD);
            #pragma unroll
            for (int j = 0; j < 2; j++)
                wmma::load_matrix_sync(bf[j], B + (wn * 32 + j * 16) * SPAD + k0, SPAD);
            #pragma unroll
            for (int i = 0; i < 2; i++)
                #pragma unroll
                for (int j = 0; j < 2; j++)
                    wmma::mma_sync(acc[i][j], af[i], bf[j], acc[i][j]);
        }
    }

    #pragma unroll
    for (int i = 0; i < 2; i++)
        #pragma unroll
        for (int j = 0; j < 2; j++) {
            float* op = probs + ((size_t)bh * SEQ + s0 + wm * 32 + i * 16) * SEQ
                        + t0 + wn * 32 + j * 16;
            wmma::store_matrix_sync(op, acc[i][j], SEQ, wmma::mem_row_major);
        }
}

// ============ softmax: fp32 in-place + bf16 copy for PV ============
__global__ __launch_bounds__(256)
void softmax_kernel(float* __restrict__ probs, __nv_bfloat16* __restrict__ pbf)
{
    float* p = probs + (size_t)blockIdx.x * SEQ;
    __nv_bfloat16* pb = pbf + (size_t)blockIdx.x * SEQ;
    const int tid = threadIdx.x;
    __shared__ float sh[8];

    float4 v[2];
    v[0] = *(const float4*)(p + tid * 8);
    v[1] = *(const float4*)(p + tid * 8 + 4);
    float mx = fmaxf(fmaxf(fmaxf(v[0].x, v[0].y), fmaxf(v[0].z, v[0].w)),
                     fmaxf(fmaxf(v[1].x, v[1].y), fmaxf(v[1].z, v[1].w)));
    #pragma unroll
    for (int o = 16; o; o >>= 1) mx = fmaxf(mx, __shfl_xor_sync(0xffffffffu, mx, o));
    if ((tid & 31) == 0) sh[tid >> 5] = mx;
    __syncthreads();
    mx = sh[0];
    #pragma unroll
    for (int i = 1; i < 8; i++) mx = fmaxf(mx, sh[i]);
    __syncthreads();

    float sum = 0.f;
    #pragma unroll
    for (int i = 0; i < 2; i++) {
        v[i].x = __expf(v[i].x - mx); v[i].y = __expf(v[i].y - mx);
        v[i].z = __expf(v[i].z - mx); v[i].w = __expf(v[i].w - mx);
        sum += (v[i].x + v[i].y) + (v[i].z + v[i].w);
    }
    #pragma unroll
    for (int o = 16; o; o >>= 1) sum += __shfl_xor_sync(0xffffffffu, sum, o);
    if ((tid & 31) == 0) sh[tid >> 5] = sum;
    __syncthreads();
    sum = 0.f;
    #pragma unroll
    for (int i = 0; i < 8; i++) sum += sh[i];
    float inv = 1.f / sum;
    #pragma unroll
    for (int i = 0; i < 2; i++) {
        v[i].x *= inv; v[i].y *= inv; v[i].z *= inv; v[i].w *= inv;
    }
    *(float4*)(p + tid * 8) = v[0];
    *(float4*)(p + tid * 8 + 4) = v[1];

    __nv_bfloat162 b0 = __floats2bfloat162_rn(v[0].x, v[0].y);
    __nv_bfloat162 b1 = __floats2bfloat162_rn(v[0].z, v[0].w);
    __nv_bfloat162 b2 = __floats2bfloat162_rn(v[1].x, v[1].y);
    __nv_bfloat162 b3 = __floats2bfloat162_rn(v[1].z, v[1].w);
    uint4 u;
    u.x = *(uint32_t*)&b0; u.y = *(uint32_t*)&b1;
    u.z = *(uint32_t*)&b2; u.w = *(uint32_t*)&b3;
    *(uint4*)(pb + tid * 8) = u;
}

// ============ ctx = P @ V via WMMA bf16, 2 CTAs/SM ============
__global__ __launch_bounds__(256, 2)
void pv_mma()
{
    __shared__ __nv_bfloat16 Pb[128 * SPAD];
    __shared__ __nv_bfloat16 Vb[64 * SPAD];
    const int tid = threadIdx.x, wid = tid >> 5;
    const int bh = blockIdx.y;
    const int b = bh / NHEAD, h = bh % NHEAD;
    const int s0 = blockIdx.x * 128;

    const __nv_bfloat16* pbase = g_pbf + ((size_t)bh * SEQ + s0) * SEQ;
    const __nv_bfloat16* vbase = g_vb + (size_t)b * SEQ * HID + h * HDIM;

    const int wm = wid & 3;
    const int wn = wid >> 2;

    wmma::fragment<wmma::accumulator, 16, 16, 16, float> acc[2][2];
    #pragma unroll
    for (int i = 0; i < 2; i++)
        #pragma unroll
        for (int j = 0; j < 2; j++)
            wmma::fill_fragment(acc[i][j], 0.f);

    for (int t0 = 0; t0 < SEQ; t0 += 64) {
        #pragma unroll
        for (int i = 0; i < 4; i++) {
            int idx = tid + i * 256;
            int r = idx >> 3, c8 = (idx & 7) * 8;
            uint4 v = *(const uint4*)(pbase + (size_t)r * SEQ + t0 + c8);
            *(uint4*)(Pb + r * SPAD + c8) = v;
        }
        #pragma unroll
        for (int i = 0; i < 2; i++) {
            int idx = tid + i * 256;
            int r = idx >> 3, c8 = (idx & 7) * 8;
            uint4 v = *(const uint4*)(vbase + (size_t)(t0 + r) * HID + c8);
            *(uint4*)(Vb + r * SPAD + c8) = v;
        }
        __syncthreads();
        #pragma unroll
        for (int k0 = 0; k0 < 64; k0 += 16) {
            wmma::fragment<wmma::matrix_a, 16, 16, 16, __nv_bfloat16, wmma::row_major> af[2];
            wmma::fragment<wmma::matrix_b, 16, 16, 16, __nv_bfloat16, wmma::row_major> bf[2];
            #pragma unroll
            for (int i = 0; i < 2; i++)
                wmma::load_matrix_sync(af[i], Pb + (wm * 32 + i * 16) * SPAD + k0, SPAD);
            #pragma unroll
            for (int j = 0; j < 2; j++)
                wmma::load_matrix_sync(bf[j], Vb + k0 * SPAD + wn * 32 + j * 16, SPAD);
            #pragma unroll
            for (int i = 0; i < 2; i++)
                #pragma unroll
                for (int j = 0; j < 2; j++)
                    wmma::mma_sync(acc[i][j], af[i], bf[j], acc[i][j]);
        }
        __syncthreads();
    }

    #pragma unroll
    for (int i = 0; i < 2; i++)
        #pragma unroll
        for (int j = 0; j < 2; j++) {
            float* op = g_ctx + (size_t)(b * SEQ + s0 + wm * 32 + i * 16) * HID
                        + h * HDIM + wn * 32 + j * 16;
            wmma::store_matrix_sync(op, acc[i][j], HID, wmma::mem_row_major);
        }
}

// ============ 'nowb' LayerNorm ============
__global__ __launch_bounds__(256)
void ln_kernel(const float* __restrict__ y, float* __restrict__ out)
{
    const float* yr = y + (size_t)blockIdx.x * HID;
    float* orow = out + (size_t)blockIdx.x * HID;
    const int tid = threadIdx.x;
    __shared__ float sh[8];

    float v[3];
    float sum = 0.f;
    #pragma unroll
    for (int i = 0; i < 3; i++) { v[i] = yr[tid + i * 256]; sum += v[i]; }
    #pragma unroll
    for (int o = 16; o; o >>= 1) sum += __shfl_xor_sync(0xffffffffu, sum, o);
    if ((tid & 31) == 0) sh[tid >> 5] = sum;
    __syncthreads();
    sum = 0.f;
    #pragma unroll
    for (int i = 0; i < 8; i++) sum += sh[i];
    float mean = sum * (1.f / HID);
    __syncthreads();

    float ss = 0.f;
    #pragma unroll
    for (int i = 0; i < 3; i++) { float d = v[i] - mean; ss += d * d; }
    #pragma unroll
    for (int o = 16; o; o >>= 1) ss += __shfl_xor_sync(0xffffffffu, ss, o);
    if ((tid & 31) == 0) sh[tid >> 5] = ss;
    __syncthreads();
    ss = 0.f;
    #pragma unroll
    for (int i = 0; i < 8; i++) ss += sh[i];
    float stdv = sqrtf(ss * (1.f / (HID - 1)));
    float inv = 1.f / (stdv + LNEPS);
    #pragma unroll
    for (int i = 0; i < 3; i++) orow[tid + i * 256] = (v[i] - mean) * inv;
}

// ---------------- launch ----------------
extern "C" void kernel_launch(void* const* d_in, const int* in_sizes, int n_in,
                              void* d_out, int out_size)
{
    const float* x  = (const float*)d_in[0];
    const float* Wq = (const float*)d_in[1];
    const float* bq = (const float*)d_in[2];
    const float* Wk = (const float*)d_in[3];
    const float* bk = (const float*)d_in[4];
    const float* Wv = (const float*)d_in[5];
    const float* bv = (const float*)d_in[6];
    const float* Wo = (const float*)d_in[7];
    const float* bo = (const float*)d_in[8];

    float* out   = (float*)d_out;
    float* probs = out + (size_t)MTOK * HID;

    float *ctx, *y;
    __nv_bfloat16 *xhi, *xlo, *qhi, *qlo, *khi, *klo, *vb, *pbf, *chi, *clo;
    cudaGetSymbolAddress((void**)&ctx, g_ctx);
    cudaGetSymbolAddress((void**)&y,   g_y);
    cudaGetSymbolAddress((void**)&xhi, g_xhi);
    cudaGetSymbolAddress((void**)&xlo, g_xlo);
    cudaGetSymbolAddress((void**)&qhi, g_qhi);
    cudaGetSymbolAddress((void**)&qlo, g_qlo);
    cudaGetSymbolAddress((void**)&khi, g_khi);
    cudaGetSymbolAddress((void**)&klo, g_klo);
    cudaGetSymbolAddress((void**)&vb,  g_vb);
    cudaGetSymbolAddress((void**)&pbf, g_pbf);
    cudaGetSymbolAddress((void**)&chi, g_chi);
    cudaGetSymbolAddress((void**)&clo, g_clo);

    cudaFuncSetAttribute(scores_mma, cudaFuncAttributeMaxDynamicSharedMemorySize, SC_SMEM);
    cudaFuncSetAttribute(proj_wmma, cudaFuncAttributeMaxDynamicSharedMemorySize, PJ_SMEM);

    const int n4 = MTOK * HID / 4;
    cvt_hilo<<<(n4 + 255) / 256, 256>>>(x, xhi, xlo, n4);

    dim3 gproj(MTOK / 128, HID / 64);   // (32, 12)
    proj_wmma<<<gproj, 256, PJ_SMEM>>>(xhi, xlo, Wq, bq, nullptr, nullptr, qhi, qlo, nullptr, 0);
    proj_wmma<<<gproj, 256, PJ_SMEM>>>(xhi, xlo, Wk, bk, nullptr, nullptr, khi, klo, nullptr, 0);
    proj_wmma<<<gproj, 256, PJ_SMEM>>>(xhi, xlo, Wv, bv, nullptr, nullptr, nullptr, nullptr, vb, 0);

    scores_mma<<<dim3(SEQ / 128, SEQ / 128, BATCH * NHEAD), 512, SC_SMEM>>>(probs);

    softmax_kernel<<<BATCH * NHEAD * SEQ, 256>>>(probs, pbf);

    pv_mma<<<dim3(SEQ / 128, BATCH * NHEAD), 256>>>();

    cvt_hilo<<<(n4 + 255) / 256, 256>>>(ctx, chi, clo, n4);

    proj_wmma<<<gproj, 256, PJ_SMEM>>>(chi, clo, Wo, bo, x, y, nullptr, nullptr, nullptr, 1);

    ln_kernel<<<MTOK, 256>>>(y, out);
}